// round 9
// baseline (speedup 1.0000x reference)
#include <cuda_runtime.h>
#include <math.h>
#include <stdint.h>

#define NUM_CLASSES 10
#define BLOCK 256
#define WARPS_PER_BLOCK (BLOCK / 32)
#define BLOCKS_PER_SM 5
#define GRID (148 * BLOCKS_PER_SM)             // 740 — co-resident via launch_bounds
#define NTHREADS (GRID * BLOCK)
#define TOTAL_WARPS (GRID * WARPS_PER_BLOCK)   // 5920
#define CHUNK_ROWS 48                          // per warp-iter: 4 u-steps x 12 rows
#define CHUNK_F4 (CHUNK_ROWS * NUM_CLASSES / 4)  // 120 float4

// log(x) = logf(x * 2^-21) + 21*ln2  (shift folded into final math)
#define LOG_SCALE (4.76837158203125e-7f)   // 2^-21
#define LOG_SHIFT 21.0

__device__ float  g_hist_partial[GRID * NUM_CLASSES];
__device__ double g_partial_log[GRID];
__device__ double g_partial_sq[GRID];
__device__ unsigned int g_hist_ready = 0;  // reset by last block each run
__device__ unsigned int g_done = 0;        // reset by last block each run

__global__ void __launch_bounds__(BLOCK, BLOCKS_PER_SM)
cse_fused_kernel(const float* __restrict__ outp, const int* __restrict__ tgt,
                 int n_rows, float* __restrict__ out) {
    __shared__ unsigned int s_hist[NUM_CLASSES];
    __shared__ float  s_cnt[NUM_CLASSES];
    __shared__ double s_rl[WARPS_PER_BLOCK];
    __shared__ double s_rq[WARPS_PER_BLOCK];
    __shared__ bool s_last;

    const int tid  = threadIdx.x;
    const int bid  = blockIdx.x;
    const int wid  = tid >> 5;
    const int lane = tid & 31;

    // ================= Phase A: histogram of target (int32 in [0,10)) ======
    if (tid < NUM_CLASSES) { s_hist[tid] = 0u; s_cnt[tid] = 0.0f; }
    __syncthreads();
    {
        unsigned int c[NUM_CLASSES];
#pragma unroll
        for (int j = 0; j < NUM_CLASSES; j++) c[j] = 0u;

        const int4* t4 = reinterpret_cast<const int4*>(tgt);
        const int n4 = n_rows >> 2;
        unsigned long long acc = 0ull;
        int since = 0;
        for (int i = bid * BLOCK + tid; i < n4; i += NTHREADS) {
            int4 v = __ldcs(&t4[i]);
            acc += 1ull << (6 * v.x);
            acc += 1ull << (6 * v.y);
            acc += 1ull << (6 * v.z);
            acc += 1ull << (6 * v.w);
            if (++since == 10) {          // <=40 increments per 6-bit field
#pragma unroll
                for (int j = 0; j < NUM_CLASSES; j++)
                    c[j] += (unsigned int)((acc >> (6 * j)) & 63ull);
                acc = 0ull; since = 0;
            }
        }
        if (since) {
#pragma unroll
            for (int j = 0; j < NUM_CLASSES; j++)
                c[j] += (unsigned int)((acc >> (6 * j)) & 63ull);
        }
        if (bid == 0 && tid == 0) {       // tail rows (n % 4)
            for (int r = (n_rows >> 2) << 2; r < n_rows; r++) c[tgt[r]]++;
        }
#pragma unroll
        for (int j = 0; j < NUM_CLASSES; j++)
            if (c[j]) atomicAdd(&s_hist[j], c[j]);
    }
    __syncthreads();
    if (tid < NUM_CLASSES)
        g_hist_partial[bid * NUM_CLASSES + tid] = (float)s_hist[tid];
    __threadfence();
    if (tid == 0) {
        atomicAdd(&g_hist_ready, 1u);
        while (*(volatile unsigned int*)&g_hist_ready < (unsigned int)GRID)
            __nanosleep(64);
        __threadfence();
    }
    __syncthreads();

    // reduce partials -> class counts (exact small integers in float)
    for (int idx = tid; idx < GRID * NUM_CLASSES; idx += BLOCK)
        atomicAdd(&s_cnt[idx % NUM_CLASSES], g_hist_partial[idx]);
    __syncthreads();

    // ================= Phase B: warp-shuffle streaming (NO smem) ============
    // Lanes 0-29 load 30 consecutive float4 (12 rows). Quintet of lanes
    // (5q..5q+4) owns rows 2q (even) and 2q+1 (odd) of the 12-row window.
    // Per-lane partial dots -> 2x shfl_down assembles full row dots.
    const int role = lane % 5;                 // meaningful for lane < 30
    const bool ld_on = lane < 30;
    const bool isA = ld_on && (role == 0);     // collector of dot_even
    const bool isB = ld_on && (role == 2);     // collector of dot_odd

    float4 coef;
    {
        int s0 = (4 * lane) % 10;
        coef.x = s_cnt[s0];
        coef.y = s_cnt[(s0 + 1) % 10];
        coef.z = s_cnt[(s0 + 2) % 10];
        coef.w = s_cnt[(s0 + 3) % 10];
    }
    const float ma1 = (role <= 2) ? 1.0f : 0.0f;   // t01 -> even-row dot
    const float ma2 = (role <= 1) ? 1.0f : 0.0f;   // t23 -> even-row dot
    const float mb1 = (role >= 3) ? 1.0f : 0.0f;   // t01 -> odd-row dot
    const float mb2 = (role >= 2) ? 1.0f : 0.0f;   // t23 -> odd-row dot

    const float4* __restrict__ in4 = reinterpret_cast<const float4*>(outp);
    const int n_chunks = n_rows / CHUNK_ROWS;
    const int gwarp = bid * WARPS_PER_BLOCK + wid;

    double acc_log = 0.0;
    double acc_sq  = 0.0;
    float  prod    = 1.0f;
    int    toggle  = 0;

    for (int ch = gwarp; ch < n_chunks; ch += TOTAL_WARPS) {
        float4 f0 = {0,0,0,0}, f1 = {0,0,0,0}, f2 = {0,0,0,0}, f3 = {0,0,0,0};
        if (ld_on) {
            const float4* g = in4 + (size_t)ch * CHUNK_F4 + lane;
            f0 = __ldcs(g +  0);
            f1 = __ldcs(g + 30);
            f2 = __ldcs(g + 60);
            f3 = __ldcs(g + 90);
        }

        float sqf = 0.0f;
#pragma unroll
        for (int u = 0; u < 4; u++) {
            float4 f = (u == 0) ? f0 : (u == 1) ? f1 : (u == 2) ? f2 : f3;

            sqf = fmaf(f.x, f.x, sqf);
            sqf = fmaf(f.y, f.y, sqf);
            sqf = fmaf(f.z, f.z, sqf);
            sqf = fmaf(f.w, f.w, sqf);

            float t01 = fmaf(f.y, coef.y, f.x * coef.x);
            float t23 = fmaf(f.w, coef.w, f.z * coef.z);
            float a = fmaf(t01, ma1, t23 * ma2);
            float b = fmaf(t01, mb1, t23 * mb2);

            float a1 = __shfl_down_sync(0xffffffffu, a, 1);
            float a2 = __shfl_down_sync(0xffffffffu, a, 2);
            float b1 = __shfl_down_sync(0xffffffffu, b, 1);
            float b2 = __shfl_down_sync(0xffffffffu, b, 2);
            float s_a = a + a1 + a2;       // valid at lanes 5q   (dot of even row)
            float s_b = b + b1 + b2;       // valid at lanes 5q+2 (dot of odd row)

            float fac = 1.0f;
            if (isA) fac = s_a * LOG_SCALE;
            if (isB) fac = s_b * LOG_SCALE;
            prod *= fac;
        }
        acc_sq += (double)sqf;

        toggle ^= 1;
        if (!toggle) {                     // 8 factors accumulated on active lanes
            acc_log += (double)logf(prod); // inactive lanes: logf(1)=0
            prod = 1.0f;
        }
    }

    if (toggle) acc_log += (double)logf(prod);

    // tail rows (n_rows % CHUNK_ROWS) directly from gmem, block 0
    const int tail_start = n_chunks * CHUNK_ROWS;
    if (bid == 0) {
        float cs[NUM_CLASSES];
#pragma unroll
        for (int j = 0; j < NUM_CLASSES; j++) cs[j] = s_cnt[j];
        for (int r = tail_start + tid; r < n_rows; r += BLOCK) {
            const float* row = outp + (size_t)r * NUM_CLASSES;
            float dot = 0.f, sq = 0.f;
#pragma unroll
            for (int j = 0; j < NUM_CLASSES; j++) {
                float x = row[j];
                dot = fmaf(x, cs[j], dot);
                sq  = fmaf(x, x, sq);
            }
            acc_sq  += (double)sq;
            acc_log += (double)logf(dot * LOG_SCALE);
        }
    }

    // ================= block reduction (deterministic order) ===============
#pragma unroll
    for (int off = 16; off; off >>= 1) {
        acc_log += __shfl_down_sync(0xffffffffu, acc_log, off);
        acc_sq  += __shfl_down_sync(0xffffffffu, acc_sq,  off);
    }
    if (lane == 0) { s_rl[wid] = acc_log; s_rq[wid] = acc_sq; }
    __syncthreads();
    if (tid == 0) {
        double a = 0.0, b = 0.0;
#pragma unroll
        for (int w = 0; w < WARPS_PER_BLOCK; w++) { a += s_rl[w]; b += s_rq[w]; }
        g_partial_log[bid] = a;
        g_partial_sq[bid]  = b;
        __threadfence();
        unsigned int tkt = atomicAdd(&g_done, 1u);
        s_last = (tkt == (unsigned int)(GRID - 1));
    }
    __syncthreads();

    // ================= last block: final scalar =============================
    if (s_last) {
        __threadfence();
        double a = 0.0, b = 0.0;
        for (int i = tid; i < GRID; i += BLOCK) {
            a += g_partial_log[i];
            b += g_partial_sq[i];
        }
#pragma unroll
        for (int off = 16; off; off >>= 1) {
            a += __shfl_down_sync(0xffffffffu, a, off);
            b += __shfl_down_sync(0xffffffffu, b, off);
        }
        if (lane == 0) { s_rl[wid] = a; s_rq[wid] = b; }
        __syncthreads();
        if (tid == 0) {
            double sa = 0.0, sb = 0.0;
#pragma unroll
            for (int w = 0; w < WARPS_PER_BLOCK; w++) { sa += s_rl[w]; sb += s_rq[w]; }
            double N = (double)n_rows;
            double mean_log_nom = sa / N + LOG_SHIFT * M_LN2;
            double log_denom = 0.5 * log(sb) + 0.5 * log(N);   // log(||o||_F * sqrt(N))
            out[0] = (float)(log_denom - mean_log_nom);
            g_done = 0;         // reset for next graph replay
            g_hist_ready = 0;
        }
    }
}

extern "C" void kernel_launch(void* const* d_in, const int* in_sizes, int n_in,
                              void* d_out, int out_size) {
    // Resolve inputs by size: outputs has NUM_CLASSES x the elements of target.
    int io = 0, it = 1;
    if (n_in >= 2 && in_sizes[1] > in_sizes[0]) { io = 1; it = 0; }
    const float* outputs = (const float*)d_in[io];
    const int*   tgt     = (const int*)d_in[it];      // int32
    const int    n_rows  = in_sizes[it];              // N samples
    float* out           = (float*)d_out;

    cse_fused_kernel<<<GRID, BLOCK>>>(outputs, tgt, n_rows, out);
}

// round 10
// speedup vs baseline: 1.2789x; 1.2789x over previous
#include <cuda_runtime.h>
#include <math.h>
#include <stdint.h>

#define NUM_CLASSES 10
#define BLOCK 256
#define WARPS_PER_BLOCK (BLOCK / 32)
#define GRID 444                       // 148 SMs * 3 — co-resident (proven R6/R8)
#define NTHREADS (GRID * BLOCK)
#define TOTAL_WARPS (GRID * WARPS_PER_BLOCK)   // 3552
#define CHUNK_ROWS 128                 // per warp-iter: 128 rows = 5120 B (10 LDG.128/lane)
#define CHUNK_F4 (CHUNK_ROWS * NUM_CLASSES / 4)  // 320 float4
#define SUB_FLOATS (64 * NUM_CLASSES)  // 640 floats per sub-buffer (R8 layout)

// log(x) = logf(x * 2^-21) + 21*ln2  (shift folded into final math)
#define LOG_SCALE (4.76837158203125e-7f)   // 2^-21
#define LOG_SHIFT 21.0

__device__ float  g_hist_partial[GRID * NUM_CLASSES];
__device__ double g_partial_log[GRID];
__device__ double g_partial_sq[GRID];
__device__ unsigned int g_hist_ready = 0;  // reset by last block each run
__device__ unsigned int g_done = 0;        // reset by last block each run

// ---- packed f32x2 helpers (Blackwell) --------------------------------------
__device__ __forceinline__ unsigned long long ffma2(unsigned long long a,
                                                    unsigned long long b,
                                                    unsigned long long c) {
    unsigned long long d;
    asm("fma.rn.f32x2 %0, %1, %2, %3;" : "=l"(d) : "l"(a), "l"(b), "l"(c));
    return d;
}
__device__ __forceinline__ unsigned long long fmul2(unsigned long long a,
                                                    unsigned long long b) {
    unsigned long long d;
    asm("mul.rn.f32x2 %0, %1, %2;" : "=l"(d) : "l"(a), "l"(b));
    return d;
}
__device__ __forceinline__ unsigned long long fpack2(float lo, float hi) {
    unsigned long long d;
    asm("mov.b64 %0, {%1, %2};" : "=l"(d) : "f"(lo), "f"(hi));
    return d;
}
__device__ __forceinline__ float funpack_sum(unsigned long long d) {
    float lo, hi;
    asm("mov.b64 {%0, %1}, %2;" : "=f"(lo), "=f"(hi) : "l"(d));
    return lo + hi;
}

// Dot + sumsq for this lane's 2 rows inside one 640-float sub-buffer (R8 layout)
__device__ __forceinline__ void rows2_dot(const float* sub, int lane,
                                          unsigned long long cp0, unsigned long long cp1,
                                          unsigned long long cp2, unsigned long long cp3,
                                          unsigned long long cp4,
                                          unsigned long long& sq2,
                                          float& dot0, float& dot1) {
    const ulonglong2* my = reinterpret_cast<const ulonglong2*>(sub) + lane * 5;
    ulonglong2 p0 = my[0];
    ulonglong2 p1 = my[1];
    ulonglong2 p2 = my[2];
    ulonglong2 p3 = my[3];
    ulonglong2 p4 = my[4];

    unsigned long long d0 = fmul2(p0.x, cp0);
    d0 = ffma2(p0.y, cp1, d0);
    d0 = ffma2(p1.x, cp2, d0);
    d0 = ffma2(p1.y, cp3, d0);
    d0 = ffma2(p2.x, cp4, d0);
    unsigned long long d1 = fmul2(p2.y, cp0);
    d1 = ffma2(p3.x, cp1, d1);
    d1 = ffma2(p3.y, cp2, d1);
    d1 = ffma2(p4.x, cp3, d1);
    d1 = ffma2(p4.y, cp4, d1);

    sq2 = ffma2(p0.x, p0.x, sq2);
    sq2 = ffma2(p0.y, p0.y, sq2);
    sq2 = ffma2(p1.x, p1.x, sq2);
    sq2 = ffma2(p1.y, p1.y, sq2);
    sq2 = ffma2(p2.x, p2.x, sq2);
    sq2 = ffma2(p2.y, p2.y, sq2);
    sq2 = ffma2(p3.x, p3.x, sq2);
    sq2 = ffma2(p3.y, p3.y, sq2);
    sq2 = ffma2(p4.x, p4.x, sq2);
    sq2 = ffma2(p4.y, p4.y, sq2);

    dot0 = funpack_sum(d0);
    dot1 = funpack_sum(d1);
}

__global__ void __launch_bounds__(BLOCK, 3)
cse_fused_kernel(const float* __restrict__ outp, const int* __restrict__ tgt,
                 int n_rows, float* __restrict__ out) {
    // per-warp private staging (5120 B each = 2 sub-buffers of R8 layout)
    __shared__ __align__(16) float s_stage[WARPS_PER_BLOCK][CHUNK_ROWS * NUM_CLASSES];
    __shared__ unsigned int s_hist[NUM_CLASSES];
    __shared__ float  s_cnt[NUM_CLASSES];
    __shared__ double s_rl[WARPS_PER_BLOCK];
    __shared__ double s_rq[WARPS_PER_BLOCK];
    __shared__ bool s_last;

    const int tid  = threadIdx.x;
    const int bid  = blockIdx.x;
    const int wid  = tid >> 5;
    const int lane = tid & 31;

    // ================= Phase A: histogram of target (int32 in [0,10)) ======
    if (tid < NUM_CLASSES) { s_hist[tid] = 0u; s_cnt[tid] = 0.0f; }
    __syncthreads();
    {
        unsigned int c[NUM_CLASSES];
#pragma unroll
        for (int j = 0; j < NUM_CLASSES; j++) c[j] = 0u;

        const int4* t4 = reinterpret_cast<const int4*>(tgt);
        const int n4 = n_rows >> 2;
        unsigned long long acc = 0ull;
        int since = 0;
        for (int i = bid * BLOCK + tid; i < n4; i += NTHREADS) {
            int4 v = __ldcs(&t4[i]);
            acc += 1ull << (6 * v.x);
            acc += 1ull << (6 * v.y);
            acc += 1ull << (6 * v.z);
            acc += 1ull << (6 * v.w);
            if (++since == 10) {          // <=40 increments per 6-bit field
#pragma unroll
                for (int j = 0; j < NUM_CLASSES; j++)
                    c[j] += (unsigned int)((acc >> (6 * j)) & 63ull);
                acc = 0ull; since = 0;
            }
        }
        if (since) {
#pragma unroll
            for (int j = 0; j < NUM_CLASSES; j++)
                c[j] += (unsigned int)((acc >> (6 * j)) & 63ull);
        }
        if (bid == 0 && tid == 0) {       // tail rows (n % 4)
            for (int r = (n_rows >> 2) << 2; r < n_rows; r++) c[tgt[r]]++;
        }
#pragma unroll
        for (int j = 0; j < NUM_CLASSES; j++)
            if (c[j]) atomicAdd(&s_hist[j], c[j]);
    }
    __syncthreads();
    if (tid < NUM_CLASSES)
        g_hist_partial[bid * NUM_CLASSES + tid] = (float)s_hist[tid];
    __threadfence();
    if (tid == 0) {
        atomicAdd(&g_hist_ready, 1u);
        while (*(volatile unsigned int*)&g_hist_ready < (unsigned int)GRID)
            __nanosleep(64);
        __threadfence();
    }
    __syncthreads();

    // reduce partials -> class counts (exact small integers in float)
    for (int idx = tid; idx < GRID * NUM_CLASSES; idx += BLOCK)
        atomicAdd(&s_cnt[idx % NUM_CLASSES], g_hist_partial[idx]);
    __syncthreads();

    // packed class-count pairs
    const unsigned long long cp0 = fpack2(s_cnt[0], s_cnt[1]);
    const unsigned long long cp1 = fpack2(s_cnt[2], s_cnt[3]);
    const unsigned long long cp2 = fpack2(s_cnt[4], s_cnt[5]);
    const unsigned long long cp3 = fpack2(s_cnt[6], s_cnt[7]);
    const unsigned long long cp4 = fpack2(s_cnt[8], s_cnt[9]);

    // ================= Phase B: warp-autonomous, 10 front-batched LDG.128 ===
    const float4* __restrict__ in4 = reinterpret_cast<const float4*>(outp);
    float4* sreg4 = reinterpret_cast<float4*>(&s_stage[wid][0]);
    const int n_chunks = n_rows / CHUNK_ROWS;
    const int gwarp = bid * WARPS_PER_BLOCK + wid;

    double acc_log = 0.0;
    unsigned long long sq2 = 0ull;
    float  prod    = 1.0f;
    int    toggle  = 0;

    for (int ch = gwarp; ch < n_chunks; ch += TOTAL_WARPS) {
        const float4* g = in4 + (size_t)ch * CHUNK_F4 + lane;
        // 10 front-batched loads — high MLP, one latency exposure per 5120 B
        float4 r0 = __ldcs(g + 0 * 32);
        float4 r1 = __ldcs(g + 1 * 32);
        float4 r2 = __ldcs(g + 2 * 32);
        float4 r3 = __ldcs(g + 3 * 32);
        float4 r4 = __ldcs(g + 4 * 32);
        float4 r5 = __ldcs(g + 5 * 32);
        float4 r6 = __ldcs(g + 6 * 32);
        float4 r7 = __ldcs(g + 7 * 32);
        float4 r8 = __ldcs(g + 8 * 32);
        float4 r9 = __ldcs(g + 9 * 32);
        sreg4[lane + 0 * 32] = r0;
        sreg4[lane + 1 * 32] = r1;
        sreg4[lane + 2 * 32] = r2;
        sreg4[lane + 3 * 32] = r3;
        sreg4[lane + 4 * 32] = r4;
        sreg4[lane + 5 * 32] = r5;
        sreg4[lane + 6 * 32] = r6;
        sreg4[lane + 7 * 32] = r7;
        sreg4[lane + 8 * 32] = r8;
        sreg4[lane + 9 * 32] = r9;
        __syncwarp();

        float dot0, dot1, dot2, dot3;
        rows2_dot(&s_stage[wid][0],          lane, cp0, cp1, cp2, cp3, cp4, sq2, dot0, dot1);
        rows2_dot(&s_stage[wid][SUB_FLOATS], lane, cp0, cp1, cp2, cp3, cp4, sq2, dot2, dot3);

        prod *= dot0 * LOG_SCALE;
        prod *= dot1 * LOG_SCALE;
        prod *= dot2 * LOG_SCALE;
        prod *= dot3 * LOG_SCALE;

        toggle ^= 1;
        if (!toggle) {                    // 8 factors accumulated
            acc_log += (double)logf(prod);
            prod = 1.0f;
        }
        __syncwarp();                     // region free for next iteration
    }

    if (toggle) acc_log += (double)logf(prod);
    double acc_sq = (double)funpack_sum(sq2);

    // tail rows (n_rows % CHUNK_ROWS) directly from gmem, block 0
    const int tail_start = n_chunks * CHUNK_ROWS;
    if (bid == 0) {
        float cs[NUM_CLASSES];
#pragma unroll
        for (int j = 0; j < NUM_CLASSES; j++) cs[j] = s_cnt[j];
        for (int r = tail_start + tid; r < n_rows; r += BLOCK) {
            const float* row = outp + (size_t)r * NUM_CLASSES;
            float dot = 0.f, sq = 0.f;
#pragma unroll
            for (int j = 0; j < NUM_CLASSES; j++) {
                float x = row[j];
                dot = fmaf(x, cs[j], dot);
                sq  = fmaf(x, x, sq);
            }
            acc_sq  += (double)sq;
            acc_log += (double)logf(dot * LOG_SCALE);
        }
    }

    // ================= block reduction (deterministic order) ===============
#pragma unroll
    for (int off = 16; off; off >>= 1) {
        acc_log += __shfl_down_sync(0xffffffffu, acc_log, off);
        acc_sq  += __shfl_down_sync(0xffffffffu, acc_sq,  off);
    }
    if (lane == 0) { s_rl[wid] = acc_log; s_rq[wid] = acc_sq; }
    __syncthreads();
    if (tid == 0) {
        double a = 0.0, b = 0.0;
#pragma unroll
        for (int w = 0; w < WARPS_PER_BLOCK; w++) { a += s_rl[w]; b += s_rq[w]; }
        g_partial_log[bid] = a;
        g_partial_sq[bid]  = b;
        __threadfence();
        unsigned int tkt = atomicAdd(&g_done, 1u);
        s_last = (tkt == (unsigned int)(GRID - 1));
    }
    __syncthreads();

    // ================= last block: final scalar =============================
    if (s_last) {
        __threadfence();
        double a = 0.0, b = 0.0;
        for (int i = tid; i < GRID; i += BLOCK) {
            a += g_partial_log[i];
            b += g_partial_sq[i];
        }
#pragma unroll
        for (int off = 16; off; off >>= 1) {
            a += __shfl_down_sync(0xffffffffu, a, off);
            b += __shfl_down_sync(0xffffffffu, b, off);
        }
        if (lane == 0) { s_rl[wid] = a; s_rq[wid] = b; }
        __syncthreads();
        if (tid == 0) {
            double sa = 0.0, sb = 0.0;
#pragma unroll
            for (int w = 0; w < WARPS_PER_BLOCK; w++) { sa += s_rl[w]; sb += s_rq[w]; }
            double N = (double)n_rows;
            double mean_log_nom = sa / N + LOG_SHIFT * M_LN2;
            double log_denom = 0.5 * log(sb) + 0.5 * log(N);   // log(||o||_F * sqrt(N))
            out[0] = (float)(log_denom - mean_log_nom);
            g_done = 0;         // reset for next graph replay
            g_hist_ready = 0;
        }
    }
}

extern "C" void kernel_launch(void* const* d_in, const int* in_sizes, int n_in,
                              void* d_out, int out_size) {
    // Resolve inputs by size: outputs has NUM_CLASSES x the elements of target.
    int io = 0, it = 1;
    if (n_in >= 2 && in_sizes[1] > in_sizes[0]) { io = 1; it = 0; }
    const float* outputs = (const float*)d_in[io];
    const int*   tgt     = (const int*)d_in[it];      // int32
    const int    n_rows  = in_sizes[it];              // N samples
    float* out           = (float*)d_out;

    cse_fused_kernel<<<GRID, BLOCK>>>(outputs, tgt, n_rows, out);
}